// round 10
// baseline (speedup 1.0000x reference)
#include <cuda_runtime.h>
#include <cuda_bf16.h>
#include <stdint.h>

// ---------------------------------------------------------------------------
// CSAA via warp-level bf16 mma.sync m16n8k16, hi/lo split precision (3-term),
// bf16 hi/lo planes in global, persistent CTAs (grid=148) with cross-slice
// cp.async pipelining for qkv / attn / restore.
// ---------------------------------------------------------------------------

#define SL    16384
#define TEN   (8 * 128 * SL)
#define TP    272
#define TILE_B 34816
#define PLANE  69632
#define NSM   148

__device__ __nv_bfloat16 g_resh[TEN], g_resl[TEN];
__device__ __nv_bfloat16 g_qh[TEN], g_ql[TEN];
__device__ __nv_bfloat16 g_kh[TEN], g_kl[TEN];
__device__ __nv_bfloat16 g_vh[TEN], g_vl[TEN];
__device__ __nv_bfloat16 g_wah[TEN], g_wal[TEN];   // w_attn planes [b][r][o][w]
__device__ float         g_att2[TEN];              // [b][o][r][h] fp32
__device__ __nv_bfloat16 g_hah[TEN], g_hal[TEN];   // h_attn planes [b][r][h*128+o]
__device__ __nv_bfloat16 g_wth[163840], g_wtl[163840];

#define W_R   0
#define W_QW  32768
#define W_KW  49152
#define W_VW  65536
#define W_QH  81920
#define W_KH  98304
#define W_VH  114688
#define W_O   131072

// ---------------- PTX helpers ----------------------------------------------
__device__ __forceinline__ uint32_t smem_u32(const void* p) {
    uint32_t a;
    asm("{ .reg .u64 t; cvta.to.shared.u64 t, %1; cvt.u32.u64 %0, t; }" : "=r"(a) : "l"(p));
    return a;
}
__device__ __forceinline__ void ldsm4(uint32_t (&r)[4], uint32_t a) {
    asm volatile("ldmatrix.sync.aligned.m8n8.x4.shared.b16 {%0,%1,%2,%3}, [%4];"
                 : "=r"(r[0]), "=r"(r[1]), "=r"(r[2]), "=r"(r[3]) : "r"(a));
}
__device__ __forceinline__ void ldsm4t(uint32_t (&r)[4], uint32_t a) {
    asm volatile("ldmatrix.sync.aligned.m8n8.x4.trans.shared.b16 {%0,%1,%2,%3}, [%4];"
                 : "=r"(r[0]), "=r"(r[1]), "=r"(r[2]), "=r"(r[3]) : "r"(a));
}
__device__ __forceinline__ void mma_bf16(float (&c)[4], const uint32_t (&a)[4],
                                         const uint32_t (&b)[2]) {
    asm volatile(
        "mma.sync.aligned.m16n8k16.row.col.f32.bf16.bf16.f32 "
        "{%0,%1,%2,%3}, {%4,%5,%6,%7}, {%8,%9}, {%0,%1,%2,%3};"
        : "+f"(c[0]), "+f"(c[1]), "+f"(c[2]), "+f"(c[3])
        : "r"(a[0]), "r"(a[1]), "r"(a[2]), "r"(a[3]), "r"(b[0]), "r"(b[1]));
}
__device__ __forceinline__ uint32_t pkbf(__nv_bfloat16 a, __nv_bfloat16 b) {
    __nv_bfloat162 t(a, b);
    return *reinterpret_cast<uint32_t*>(&t);
}
__device__ __forceinline__ void cpa16(uint32_t d, const void* s) {
    asm volatile("cp.async.cg.shared.global [%0], [%1], 16;" :: "r"(d), "l"(s) : "memory");
}
__device__ __forceinline__ void cpa_commit() {
    asm volatile("cp.async.commit_group;" ::: "memory");
}
template <int N>
__device__ __forceinline__ void cpa_wait() {
    asm volatile("cp.async.wait_group %0;" :: "n"(N) : "memory");
}

// rows [r0,r1) of a hi/lo plane pair -> smem tiles
__device__ __forceinline__ void cpa_rows(uint32_t sdst, const __nv_bfloat16* gh,
        const __nv_bfloat16* gl, long grs, int r0, int r1, int tid) {
    int n = (r1 - r0) * 16;
    for (int i = tid; i < n; i += 512) {
        int row = r0 + (i >> 4), cc = i & 15;
        uint32_t d = sdst + row * TP + cc * 16;
        cpa16(d, (const char*)(gh + (long)row * grs) + cc * 16);
        cpa16(d + TILE_B, (const char*)(gl + (long)row * grs) + cc * 16);
    }
}
// fp32 global -> hi/lo smem tiles (resize conv input)
__device__ __forceinline__ void load_hilo_f32(char* sm, int off, const float* __restrict__ g,
                                              long gs, int tid) {
    for (int i = tid * 4; i < 16384; i += 2048) {
        int row = i >> 7, col = i & 127;
        float4 x = *(const float4*)(g + (long)row * gs + col);
        __nv_bfloat16 h0 = __float2bfloat16(x.x), h1 = __float2bfloat16(x.y);
        __nv_bfloat16 h2 = __float2bfloat16(x.z), h3 = __float2bfloat16(x.w);
        __nv_bfloat16 l0 = __float2bfloat16(x.x - __bfloat162float(h0));
        __nv_bfloat16 l1 = __float2bfloat16(x.y - __bfloat162float(h1));
        __nv_bfloat16 l2 = __float2bfloat16(x.z - __bfloat162float(h2));
        __nv_bfloat16 l3 = __float2bfloat16(x.w - __bfloat162float(h3));
        char* p = sm + off + row * TP + col * 2;
        *(uint2*)p = make_uint2(pkbf(h0, h1), pkbf(h2, h3));
        *(uint2*)(p + TILE_B) = make_uint2(pkbf(l0, l1), pkbf(l2, l3));
    }
}

// ---------------- warp GEMM 128x128x128, 16 warps (4x4), 3-term split -------
template <bool BT>
__device__ __forceinline__ void wgemm(uint32_t sa, uint32_t sb, float (&C)[2][4][4],
                                      int lane, int wm, int wn) {
    const int lh = lane & 15, lq = lane >> 4;
#pragma unroll
    for (int k0 = 0; k0 < 128; k0 += 16) {
        uint32_t ah[2][4], al[2][4];
#pragma unroll
        for (int mt = 0; mt < 2; ++mt) {
            uint32_t addr = sa + (wm * 32 + mt * 16 + lh) * TP + (k0 + lq * 8) * 2;
            ldsm4(ah[mt], addr);
            ldsm4(al[mt], addr + TILE_B);
        }
        uint32_t bh[4][2], bl[4][2];
#pragma unroll
        for (int ng = 0; ng < 2; ++ng) {
            uint32_t r[4], rl[4], addr;
            if (BT) {
                addr = sb + (k0 + lh) * TP + (wn * 32 + ng * 16 + lq * 8) * 2;
                ldsm4t(r, addr);
                ldsm4t(rl, addr + TILE_B);
            } else {
                addr = sb + (wn * 32 + ng * 16 + lq * 8 + (lane & 7)) * TP +
                       (k0 + ((lane >> 3) & 1) * 8) * 2;
                ldsm4(r, addr);
                ldsm4(rl, addr + TILE_B);
            }
            bh[2 * ng][0] = r[0];     bh[2 * ng][1] = r[1];
            bh[2 * ng + 1][0] = r[2]; bh[2 * ng + 1][1] = r[3];
            bl[2 * ng][0] = rl[0];    bl[2 * ng][1] = rl[1];
            bl[2 * ng + 1][0] = rl[2]; bl[2 * ng + 1][1] = rl[3];
        }
#pragma unroll
        for (int mt = 0; mt < 2; ++mt)
#pragma unroll
            for (int nb = 0; nb < 4; ++nb) {
                mma_bf16(C[mt][nb], ah[mt], bh[nb]);
                mma_bf16(C[mt][nb], al[mt], bh[nb]);
                mma_bf16(C[mt][nb], ah[mt], bl[nb]);
            }
    }
}

// ---------------- fragment-direct epilogues ---------------------------------
__device__ __forceinline__ void store_planes(float (&C)[2][4][4],
        __nv_bfloat16* __restrict__ ph, __nv_bfloat16* __restrict__ pl,
        long rstr, const float* __restrict__ bias, int lane, int wm, int wn) {
    const int c0 = wn * 32 + 2 * (lane & 3);
#pragma unroll
    for (int mt = 0; mt < 2; ++mt) {
        int r0 = wm * 32 + mt * 16 + (lane >> 2);
#pragma unroll
        for (int h = 0; h < 2; ++h) {
            int row = r0 + h * 8;
            float bv = bias ? bias[row] : 0.f;
#pragma unroll
            for (int nb = 0; nb < 4; ++nb) {
                float v0 = C[mt][nb][2 * h] + bv, v1 = C[mt][nb][2 * h + 1] + bv;
                __nv_bfloat16 h0 = __float2bfloat16(v0), h1 = __float2bfloat16(v1);
                __nv_bfloat16 l0 = __float2bfloat16(v0 - __bfloat162float(h0));
                __nv_bfloat16 l1 = __float2bfloat16(v1 - __bfloat162float(h1));
                long e = (long)row * rstr + c0 + nb * 8;
                *(uint32_t*)(ph + e) = pkbf(h0, h1);
                *(uint32_t*)(pl + e) = pkbf(l0, l1);
            }
        }
    }
}
__device__ __forceinline__ void store_f32(float (&C)[2][4][4], float* __restrict__ out,
        long rstr, const float* __restrict__ bias, int lane, int wm, int wn) {
    const int c0 = wn * 32 + 2 * (lane & 3);
#pragma unroll
    for (int mt = 0; mt < 2; ++mt) {
        int r0 = wm * 32 + mt * 16 + (lane >> 2);
#pragma unroll
        for (int h = 0; h < 2; ++h) {
            int row = r0 + h * 8;
            float bv = bias ? bias[row] : 0.f;
#pragma unroll
            for (int nb = 0; nb < 4; ++nb)
                *(float2*)(out + (long)row * rstr + c0 + nb * 8) =
                    make_float2(C[mt][nb][2 * h] + bv, C[mt][nb][2 * h + 1] + bv);
        }
    }
}

// ---------------- K0: weight prep -------------------------------------------
__global__ void prep_w(const float* s0, const float* s1, const float* s2,
                       const float* s3, const float* s4, const float* s5,
                       const float* s6, const float* s7) {
    const float* srcs[8] = {s0, s1, s2, s3, s4, s5, s6, s7};
    const int offs[9] = {W_R, W_QW, W_KW, W_VW, W_QH, W_KH, W_VH, W_O, 163840};
    int m = blockIdx.y;
    const float* s = srcs[m];
    int base = offs[m], n = offs[m + 1] - offs[m];
    for (int i = blockIdx.x * blockDim.x + threadIdx.x; i < n;
         i += gridDim.x * blockDim.x) {
        float v = s[i];
        __nv_bfloat16 h = __float2bfloat16(v);
        g_wth[base + i] = h;
        g_wtl[base + i] = __float2bfloat16(v - __bfloat162float(h));
    }
}

// ---------------- K1: resize conv (unchanged structure) ----------------------
__global__ void __launch_bounds__(512, 1)
conv_resize(const float* __restrict__ x, const float* __restrict__ bias) {
    extern __shared__ char sm[];
    const int tid = threadIdx.x, lane = tid & 31, w = tid >> 5;
    const int wm = w >> 2, wn = w & 3;
    const uint32_t su = smem_u32(sm);
    const int n0 = blockIdx.x * 128, b = blockIdx.z;

    float C[2][4][4] = {};
    for (int kh = 0; kh < 2; ++kh) {
        cpa_rows(su, g_wth + W_R + kh * 128, g_wtl + W_R + kh * 128, 256, 0, 128, tid);
        cpa_commit();
        load_hilo_f32(sm, PLANE, x + (size_t)b * 256 * SL + (size_t)kh * 128 * SL + n0,
                      SL, tid);
        cpa_wait<0>();
        __syncthreads();
        wgemm<true>(su, su + PLANE, C, lane, wm, wn);
        __syncthreads();
    }
    long base = (size_t)b * 128 * SL + n0;
    store_planes(C, g_resh + base, g_resl + base, SL, bias, lane, wm, wn);
}

// ---------------- K2: persistent QKV ----------------------------------------
// grid NSM.  slices 0..1023 = b*128+r.  bt=1: width (KxN trans), 0: height.
__global__ void __launch_bounds__(512, 1)
qkv_p(const __nv_bfloat16* __restrict__ xh, const __nv_bfloat16* __restrict__ xl,
      int w0, int w1, int w2,
      const float* __restrict__ bq, const float* __restrict__ bk,
      const float* __restrict__ bv, int bt) {
    extern __shared__ char sm[];
    const int tid = threadIdx.x, lane = tid & 31, w = tid >> 5;
    const int wm = w >> 2, wn = w & 3;
    const uint32_t su = smem_u32(sm);
    const int G = gridDim.x;

    uint32_t oX = 0, oN = PLANE;
    const uint32_t oW = 2 * PLANE;

    int s0 = blockIdx.x;
    if (s0 < 1024) {
        cpa_rows(su + oX, xh + (size_t)s0 * SL, xl + (size_t)s0 * SL, 128, 0, 128, tid);
        cpa_rows(su + oW, g_wth + w0, g_wtl + w0, 128, 0, 128, tid);
        cpa_commit();   // g: X(s0) + Wq
    }
    for (int s = blockIdx.x; s < 1024; s += G) {
        const int nxt = s + G;
        const int b = s >> 7, r = s & 127;
        const long obase = (size_t)b * 128 * SL + (size_t)r * 128;
        const __nv_bfloat16* nxh = xh + (size_t)nxt * SL;
        const __nv_bfloat16* nxl = xl + (size_t)nxt * SL;

        cpa_wait<0>();
        __syncthreads();
        float C0[2][4][4] = {};
        if (bt) wgemm<true>(su + oW, su + oX, C0, lane, wm, wn);
        else    wgemm<false>(su + oW, su + oX, C0, lane, wm, wn);
        __syncthreads();
        cpa_rows(su + oW, g_wth + w1, g_wtl + w1, 128, 0, 128, tid);
        if (nxt < 1024) cpa_rows(su + oN, nxh, nxl, 128, 0, 43, tid);
        cpa_commit();
        store_planes(C0, g_qh + obase, g_ql + obase, SL, bq, lane, wm, wn);

        cpa_wait<0>();
        __syncthreads();
        float C1[2][4][4] = {};
        if (bt) wgemm<true>(su + oW, su + oX, C1, lane, wm, wn);
        else    wgemm<false>(su + oW, su + oX, C1, lane, wm, wn);
        __syncthreads();
        cpa_rows(su + oW, g_wth + w2, g_wtl + w2, 128, 0, 128, tid);
        if (nxt < 1024) cpa_rows(su + oN, nxh, nxl, 128, 43, 86, tid);
        cpa_commit();
        store_planes(C1, g_kh + obase, g_kl + obase, SL, bk, lane, wm, wn);

        cpa_wait<0>();
        __syncthreads();
        float C2[2][4][4] = {};
        if (bt) wgemm<true>(su + oW, su + oX, C2, lane, wm, wn);
        else    wgemm<false>(su + oW, su + oX, C2, lane, wm, wn);
        __syncthreads();
        if (nxt < 1024) {
            cpa_rows(su + oW, g_wth + w0, g_wtl + w0, 128, 0, 128, tid);
            cpa_rows(su + oN, nxh, nxl, 128, 86, 128, tid);
            cpa_commit();
        }
        store_planes(C2, g_vh + obase, g_vl + obase, SL, bv, lane, wm, wn);

        uint32_t t = oX; oX = oN; oN = t;
    }
}

// ---------------- K3: persistent attention -----------------------------------
// grid NSM.  slices 0..1023 = b*128+o.  mode0 -> wattn planes; mode1 -> att2.
#define T_RED  208896
__global__ void __launch_bounds__(512, 1)
attn_p(int mode) {
    extern __shared__ char sm[];
    const int tid = threadIdx.x, lane = tid & 31, w = tid >> 5;
    const int wm = w >> 2, wn = w & 3;
    const uint32_t su = smem_u32(sm);
    const int G = gridDim.x;
    float* red  = (float*)(sm + T_RED);
    float* red2 = (float*)(sm + T_RED + 2048);

    uint32_t oQ = 0, oK = PLANE;
    const uint32_t oV = 2 * PLANE;

    int s0 = blockIdx.x;
    if (s0 < 1024) {
        const size_t sb = (size_t)s0 * SL;
        cpa_rows(su + oQ, g_qh + sb, g_ql + sb, 128, 0, 128, tid);
        cpa_commit();
        cpa_rows(su + oK, g_kh + sb, g_kl + sb, 128, 0, 128, tid);
        cpa_commit();
        cpa_rows(su + oV, g_vh + sb, g_vl + sb, 128, 0, 128, tid);
        cpa_commit();
    }
    for (int s = blockIdx.x; s < 1024; s += G) {
        const int nxt = s + G;
        const int b = s >> 7, o = s & 127;
        const size_t nb_ = (size_t)nxt * SL;

        cpa_wait<1>();                      // Q(s), K(s) ready; V(s) may pend
        __syncthreads();
        float C[2][4][4] = {};
        wgemm<false>(su + oQ, su + oK, C, lane, wm, wn);   // S = Q K^T
        __syncthreads();
        if (nxt < 1024) {                   // Q(nxt) into freed K buffer
            cpa_rows(su + oK, g_qh + nb_, g_ql + nb_, 128, 0, 128, tid);
            cpa_commit();
        }

        // ---- softmax, P -> Q buffer ----
        int rows_[2][2];
        float inv_[2][2];
#pragma unroll
        for (int mt = 0; mt < 2; ++mt)
#pragma unroll
            for (int h = 0; h < 2; ++h) {
                int row = wm * 32 + mt * 16 + (lane >> 2) + h * 8;
                rows_[mt][h] = row;
                float m = -3.4e38f;
#pragma unroll
                for (int nb = 0; nb < 4; ++nb)
                    m = fmaxf(m, fmaxf(C[mt][nb][2 * h], C[mt][nb][2 * h + 1]));
                m = fmaxf(m, __shfl_xor_sync(0xffffffffu, m, 1));
                m = fmaxf(m, __shfl_xor_sync(0xffffffffu, m, 2));
                if ((lane & 3) == 0) red[wn * 128 + row] = m;
            }
        __syncthreads();
#pragma unroll
        for (int mt = 0; mt < 2; ++mt)
#pragma unroll
            for (int h = 0; h < 2; ++h) {
                int row = rows_[mt][h];
                float m = fmaxf(fmaxf(red[row], red[128 + row]),
                                fmaxf(red[256 + row], red[384 + row]));
                float sum = 0.f;
#pragma unroll
                for (int nb = 0; nb < 4; ++nb) {
                    float e0 = __expf(C[mt][nb][2 * h] - m);
                    float e1 = __expf(C[mt][nb][2 * h + 1] - m);
                    C[mt][nb][2 * h] = e0;
                    C[mt][nb][2 * h + 1] = e1;
                    sum += e0 + e1;
                }
                sum += __shfl_xor_sync(0xffffffffu, sum, 1);
                sum += __shfl_xor_sync(0xffffffffu, sum, 2);
                if ((lane & 3) == 0) red2[wn * 128 + row] = sum;
            }
        __syncthreads();
#pragma unroll
        for (int mt = 0; mt < 2; ++mt)
#pragma unroll
            for (int h = 0; h < 2; ++h) {
                int row = rows_[mt][h];
                inv_[mt][h] = 1.f / (red2[row] + red2[128 + row] +
                                     red2[256 + row] + red2[384 + row]);
            }
        const int c0 = wn * 32 + 2 * (lane & 3);
#pragma unroll
        for (int mt = 0; mt < 2; ++mt)
#pragma unroll
            for (int h = 0; h < 2; ++h) {
                int row = rows_[mt][h];
                float iv = inv_[mt][h];
#pragma unroll
                for (int nb = 0; nb < 4; ++nb) {
                    float p0 = C[mt][nb][2 * h] * iv, p1 = C[mt][nb][2 * h + 1] * iv;
                    __nv_bfloat16 h0 = __float2bfloat16(p0), h1 = __float2bfloat16(p1);
                    __nv_bfloat16 l0 = __float2bfloat16(p0 - __bfloat162float(h0));
                    __nv_bfloat16 l1 = __float2bfloat16(p1 - __bfloat162float(h1));
                    char* pp = sm + oQ + row * TP + (c0 + nb * 8) * 2;
                    *(uint32_t*)pp = pkbf(h0, h1);
                    *(uint32_t*)(pp + TILE_B) = pkbf(l0, l1);
                }
            }
        if (nxt < 1024) cpa_wait<1>();      // V(s) done; Q(nxt) pending
        else            cpa_wait<0>();
        __syncthreads();                    // P visible + V ready

        float O[2][4][4] = {};
        wgemm<true>(su + oQ, su + oV, O, lane, wm, wn);    // O = P V
        __syncthreads();
        if (nxt < 1024) {                   // K(nxt) into freed P/Q buffer, V(nxt)
            cpa_rows(su + oQ, g_kh + nb_, g_kl + nb_, 128, 0, 128, tid);
            cpa_commit();
            cpa_rows(su + oV, g_vh + nb_, g_vl + nb_, 128, 0, 128, tid);
            cpa_commit();
        }

        if (mode == 0) {
            long base = (size_t)b * 128 * SL + (size_t)o * 128;
            store_planes(O, g_wah + base, g_wal + base, SL, nullptr, lane, wm, wn);
        } else {
            store_f32(O, g_att2 + (size_t)s * SL, 128, nullptr, lane, wm, wn);
        }
        uint32_t t = oQ; oQ = oK; oK = t;   // next: Q in old-K buffer, K in old-Q
    }
}

// ---------------- K4: transpose att2 -> h_attn planes ------------------------
__global__ void trans_k(const float* __restrict__ in) {
    __shared__ float t[32][33];
    const int slice = blockIdx.z;
    const int b = slice >> 7, r = slice & 127;
    const int o0 = blockIdx.x * 32, h0 = blockIdx.y * 32;
#pragma unroll
    for (int i = threadIdx.y; i < 32; i += 8)
        t[i][threadIdx.x] =
            in[(((size_t)b * 128 + o0 + i) * 128 + r) * 128 + h0 + threadIdx.x];
    __syncthreads();
#pragma unroll
    for (int i = threadIdx.y; i < 32; i += 8) {
        float v = t[threadIdx.x][i];
        size_t e = ((size_t)b * 128 + r) * SL + (h0 + i) * 128 + o0 + threadIdx.x;
        __nv_bfloat16 h = __float2bfloat16(v);
        g_hah[e] = h;
        g_hal[e] = __float2bfloat16(v - __bfloat162float(h));
    }
}

// ---------------- K5: persistent restore conv --------------------------------
// work w in [0,2048): m0=(w&1)*128, rest=w>>1, b=rest>>7, n0=(rest&127)*128.
// grid NSM (even stride keeps m0 constant per CTA -> W resident).
__global__ void __launch_bounds__(512, 1)
restore_p(float* __restrict__ out, const float* __restrict__ bias) {
    extern __shared__ char sm[];
    const int tid = threadIdx.x, lane = tid & 31, w = tid >> 5;
    const int wm = w >> 2, wn = w & 3;
    const uint32_t su = smem_u32(sm);
    const int G = gridDim.x;
    const uint32_t oW = 2 * PLANE;
    const int m0 = (blockIdx.x & 1) * 128;

    int w0 = blockIdx.x;
    if (w0 < 2048) {
        int rest = w0 >> 1, b = rest >> 7, n0 = (rest & 127) * 128;
        cpa_rows(su + oW, g_wth + W_O + m0 * 128, g_wtl + W_O + m0 * 128, 128, 0, 128, tid);
        cpa_rows(su, g_hah + (size_t)b * 128 * SL + n0,
                 g_hal + (size_t)b * 128 * SL + n0, SL, 0, 128, tid);
        cpa_commit();                        // g0: W + X(w0)
        int w1 = w0 + G;
        if (w1 < 2048) {
            int rest1 = w1 >> 1, b1 = rest1 >> 7, n1 = (rest1 & 127) * 128;
            cpa_rows(su + PLANE, g_hah + (size_t)b1 * 128 * SL + n1,
                     g_hal + (size_t)b1 * 128 * SL + n1, SL, 0, 128, tid);
            cpa_commit();                    // g1: X(w1)
        }
    }
    int it = 0;
    for (int wk = blockIdx.x; wk < 2048; wk += G, ++it) {
        const int nxt = wk + G, nxt2 = wk + 2 * G;
        const int rest = wk >> 1, b = rest >> 7, n0 = (rest & 127) * 128;
        const uint32_t oX = (it & 1) ? PLANE : 0;

        if (nxt < 2048) cpa_wait<1>();       // X(wk)+W done; X(nxt) may pend
        else            cpa_wait<0>();
        __syncthreads();
        float C[2][4][4] = {};
        wgemm<true>(su + oW, su + oX, C, lane, wm, wn);
        __syncthreads();
        if (nxt2 < 2048) {
            int rest2 = nxt2 >> 1, b2 = rest2 >> 7, n2 = (rest2 & 127) * 128;
            cpa_rows(su + oX, g_hah + (size_t)b2 * 128 * SL + n2,
                     g_hal + (size_t)b2 * 128 * SL + n2, SL, 0, 128, tid);
            cpa_commit();
        }
        store_f32(C, out + (size_t)b * 256 * SL + (size_t)m0 * SL + n0, SL,
                  bias + m0, lane, wm, wn);
    }
}

// ---------------------------------------------------------------------------
extern "C" void kernel_launch(void* const* d_in, const int* in_sizes, int n_in,
                              void* d_out, int out_size) {
    const float* x   = (const float*)d_in[0];
    const float* Wr  = (const float*)d_in[1];
    const float* br  = (const float*)d_in[2];
    const float* Wqw = (const float*)d_in[3];
    const float* bqw = (const float*)d_in[4];
    const float* Wkw = (const float*)d_in[5];
    const float* bkw = (const float*)d_in[6];
    const float* Wvw = (const float*)d_in[7];
    const float* bvw = (const float*)d_in[8];
    const float* Wqh = (const float*)d_in[9];
    const float* bqh = (const float*)d_in[10];
    const float* Wkh = (const float*)d_in[11];
    const float* bkh = (const float*)d_in[12];
    const float* Wvh = (const float*)d_in[13];
    const float* bvh = (const float*)d_in[14];
    const float* Wo  = (const float*)d_in[15];
    const float* bo  = (const float*)d_in[16];
    float* out = (float*)d_out;

    void* p;
    cudaGetSymbolAddress(&p, g_att2);
    float* att2 = (float*)p;
    void* prh; cudaGetSymbolAddress(&prh, g_resh);
    void* prl; cudaGetSymbolAddress(&prl, g_resl);
    void* pwh; cudaGetSymbolAddress(&pwh, g_wah);
    void* pwl; cudaGetSymbolAddress(&pwl, g_wal);

    const int SM_CONV = 2 * PLANE;             // 139264
    const int SM_3P   = 3 * PLANE;             // 208896
    const int SM_ATT  = 3 * PLANE + 4096;      // 212992
    cudaFuncSetAttribute((const void*)conv_resize,
                         cudaFuncAttributeMaxDynamicSharedMemorySize, SM_CONV);
    cudaFuncSetAttribute((const void*)qkv_p,
                         cudaFuncAttributeMaxDynamicSharedMemorySize, SM_3P);
    cudaFuncSetAttribute((const void*)attn_p,
                         cudaFuncAttributeMaxDynamicSharedMemorySize, SM_ATT);
    cudaFuncSetAttribute((const void*)restore_p,
                         cudaFuncAttributeMaxDynamicSharedMemorySize, SM_3P);

    prep_w<<<dim3(64, 8), 256>>>(Wr, Wqw, Wkw, Wvw, Wqh, Wkh, Wvh, Wo);
    conv_resize<<<dim3(128, 1, 8), 512, SM_CONV>>>(x, br);
    qkv_p<<<NSM, 512, SM_3P>>>((const __nv_bfloat16*)prh, (const __nv_bfloat16*)prl,
                               W_QW, W_KW, W_VW, bqw, bkw, bvw, 1);
    attn_p<<<NSM, 512, SM_ATT>>>(0);
    qkv_p<<<NSM, 512, SM_3P>>>((const __nv_bfloat16*)pwh, (const __nv_bfloat16*)pwl,
                               W_QH, W_KH, W_VH, bqh, bkh, bvh, 0);
    attn_p<<<NSM, 512, SM_ATT>>>(1);
    trans_k<<<dim3(4, 4, 1024), dim3(32, 8)>>>(att2);
    restore_p<<<NSM, 512, SM_3P>>>(out, bo);
}

// round 13
// speedup vs baseline: 1.0376x; 1.0376x over previous
#include <cuda_runtime.h>
#include <cuda_bf16.h>
#include <stdint.h>

// ---------------------------------------------------------------------------
// CSAA, bf16 mma.sync m16n8k16 hi/lo 3-term split. All GEMM operands live in
// gmem as 64KB tile-pairs (hi 32KB + lo 32KB), XOR-swizzled so ONE
// cp.async.bulk per tile lands ldmatrix-ready in smem. Removes the
// ~12k-LDGSTS-per-slice issue tax measured in rounds 7-10.
// ---------------------------------------------------------------------------

#define SL     16384
#define TENP   (1024 * 32768)
#define PAIR_B 65536
#define LO_B   32768
#define NSM    148

__device__ __nv_bfloat16 g_res[TENP];
__device__ __nv_bfloat16 g_q[TENP];
__device__ __nv_bfloat16 g_k[TENP];
__device__ __nv_bfloat16 g_v[TENP];
__device__ __nv_bfloat16 g_wa[TENP];
__device__ __nv_bfloat16 g_ha[TENP];
__device__ float         g_att2[8 * 128 * SL];
__device__ __nv_bfloat16 g_wt[10 * 32768];
// weight tiles: 0,1=Wr(kh)  2,3,4=Wqw,Wkw,Wvw  5,6,7=Wqh,Wkh,Wvh  8,9=Wo(m0)

// ---------------- helpers ----------------------------------------------------
__device__ __forceinline__ uint32_t smem_u32(const void* p) {
    uint32_t a;
    asm("{ .reg .u64 t; cvta.to.shared.u64 t, %1; cvt.u32.u64 %0, t; }" : "=r"(a) : "l"(p));
    return a;
}
__device__ __forceinline__ uint32_t swoff(uint32_t row, uint32_t col) {
    uint32_t seg = col >> 3;
    uint32_t sw = (seg & 8u) | ((seg ^ row) & 7u);
    return row * 256u + sw * 16u + (col & 7u) * 2u;
}
__device__ __forceinline__ void ldsm4(uint32_t (&r)[4], uint32_t a) {
    asm volatile("ldmatrix.sync.aligned.m8n8.x4.shared.b16 {%0,%1,%2,%3}, [%4];"
                 : "=r"(r[0]), "=r"(r[1]), "=r"(r[2]), "=r"(r[3]) : "r"(a));
}
__device__ __forceinline__ void ldsm4t(uint32_t (&r)[4], uint32_t a) {
    asm volatile("ldmatrix.sync.aligned.m8n8.x4.trans.shared.b16 {%0,%1,%2,%3}, [%4];"
                 : "=r"(r[0]), "=r"(r[1]), "=r"(r[2]), "=r"(r[3]) : "r"(a));
}
__device__ __forceinline__ void mma_bf16(float (&c)[4], const uint32_t (&a)[4],
                                         const uint32_t (&b)[2]) {
    asm volatile(
        "mma.sync.aligned.m16n8k16.row.col.f32.bf16.bf16.f32 "
        "{%0,%1,%2,%3}, {%4,%5,%6,%7}, {%8,%9}, {%0,%1,%2,%3};"
        : "+f"(c[0]), "+f"(c[1]), "+f"(c[2]), "+f"(c[3])
        : "r"(a[0]), "r"(a[1]), "r"(a[2]), "r"(a[3]), "r"(b[0]), "r"(b[1]));
}
__device__ __forceinline__ uint32_t pkbf(__nv_bfloat16 a, __nv_bfloat16 b) {
    __nv_bfloat162 t(a, b);
    return *reinterpret_cast<uint32_t*>(&t);
}
#define MBI(a, c) asm volatile("mbarrier.init.shared.b64 [%0], %1;" :: "r"(a), "r"(c) : "memory")
#define MBX(a, n) asm volatile("mbarrier.arrive.expect_tx.shared.b64 _, [%0], %1;" :: "r"(a), "r"(n) : "memory")
#define MBW(a, par) do {                                                          \
    uint32_t _m = (a), _p = (uint32_t)(par), _d;                                  \
    asm volatile("{ .reg .pred p; mbarrier.try_wait.parity.shared.b64 p, [%1], %2; selp.b32 %0,1,0,p; }" \
        : "=r"(_d) : "r"(_m), "r"(_p) : "memory");                                \
    if (!_d) {                                                                    \
        asm volatile("{ .reg .pred P1; WL%=: mbarrier.try_wait.parity.shared.b64 P1, [%0], %1; @P1 bra.uni WD%=; bra.uni WL%=; WD%=: }" \
            :: "r"(_m), "r"(_p) : "memory");                                      \
    }                                                                             \
} while (0)
__device__ __forceinline__ void bulk_g2s(uint32_t dst, const void* src, uint32_t bytes,
                                         uint32_t mbar) {
    asm volatile(
        "cp.async.bulk.shared::cluster.global.mbarrier::complete_tx::bytes [%0], [%1], %2, [%3];"
        :: "r"(dst), "l"(src), "r"(bytes), "r"(mbar) : "memory");
}
#define FENCE_ASY() asm volatile("fence.proxy.async.shared::cta;" ::: "memory")

// ---------------- warp GEMM 128x128x128, 16 warps (4x4), 3-term split --------
template <bool BT>
__device__ __forceinline__ void wgemm(uint32_t sa, uint32_t sb, float (&C)[2][4][4],
                                      int lane, int wm, int wn) {
    const int lh = lane & 15, lq = lane >> 4;
#pragma unroll
    for (int k0 = 0; k0 < 128; k0 += 16) {
        uint32_t ah[2][4], al[2][4];
#pragma unroll
        for (int mt = 0; mt < 2; ++mt) {
            uint32_t addr = sa + swoff(wm * 32 + mt * 16 + lh, k0 + lq * 8);
            ldsm4(ah[mt], addr);
            ldsm4(al[mt], addr + LO_B);
        }
        uint32_t bh[4][2], bl[4][2];
#pragma unroll
        for (int ng = 0; ng < 2; ++ng) {
            uint32_t r[4], rl[4], addr;
            if (BT) {
                addr = sb + swoff(k0 + lh, wn * 32 + ng * 16 + lq * 8);
                ldsm4t(r, addr);
                ldsm4t(rl, addr + LO_B);
            } else {
                addr = sb + swoff(wn * 32 + ng * 16 + lq * 8 + (lane & 7),
                                  k0 + ((lane >> 3) & 1) * 8);
                ldsm4(r, addr);
                ldsm4(rl, addr + LO_B);
            }
            bh[2 * ng][0] = r[0];     bh[2 * ng][1] = r[1];
            bh[2 * ng + 1][0] = r[2]; bh[2 * ng + 1][1] = r[3];
            bl[2 * ng][0] = rl[0];    bl[2 * ng][1] = rl[1];
            bl[2 * ng + 1][0] = rl[2]; bl[2 * ng + 1][1] = rl[3];
        }
#pragma unroll
        for (int mt = 0; mt < 2; ++mt)
#pragma unroll
            for (int nb = 0; nb < 4; ++nb) {
                mma_bf16(C[mt][nb], ah[mt], bh[nb]);
                mma_bf16(C[mt][nb], al[mt], bh[nb]);
                mma_bf16(C[mt][nb], ah[mt], bl[nb]);
            }
    }
}

// producer: fragments -> swizzled gmem tile pairs. gp = slice-0 pair base of
// target group; fragment row rf selects target slice (stride PAIR_B); trow =
// CTA-constant row within each target tile.
__device__ __forceinline__ void store_sw(float (&C)[2][4][4], char* gp, uint32_t trow,
                                         const float* bias, int lane, int wm, int wn) {
    const int c0 = wn * 32 + 2 * (lane & 3);
#pragma unroll
    for (int mt = 0; mt < 2; ++mt) {
        int r0 = wm * 32 + mt * 16 + (lane >> 2);
#pragma unroll
        for (int h = 0; h < 2; ++h) {
            int rf = r0 + h * 8;
            float bv = bias ? bias[rf] : 0.f;
#pragma unroll
            for (int nb = 0; nb < 4; ++nb) {
                float v0 = C[mt][nb][2 * h] + bv, v1 = C[mt][nb][2 * h + 1] + bv;
                __nv_bfloat16 h0 = __float2bfloat16(v0), h1 = __float2bfloat16(v1);
                __nv_bfloat16 l0 = __float2bfloat16(v0 - __bfloat162float(h0));
                __nv_bfloat16 l1 = __float2bfloat16(v1 - __bfloat162float(h1));
                char* base = gp + (long)rf * PAIR_B + swoff(trow, c0 + nb * 8);
                *(uint32_t*)base = pkbf(h0, h1);
                *(uint32_t*)(base + LO_B) = pkbf(l0, l1);
            }
        }
    }
}
__device__ __forceinline__ void store_f32(float (&C)[2][4][4], float* __restrict__ out,
        long rstr, const float* __restrict__ bias, int lane, int wm, int wn) {
    const int c0 = wn * 32 + 2 * (lane & 3);
#pragma unroll
    for (int mt = 0; mt < 2; ++mt) {
        int r0 = wm * 32 + mt * 16 + (lane >> 2);
#pragma unroll
        for (int h = 0; h < 2; ++h) {
            int row = r0 + h * 8;
            float bv = bias ? bias[row] : 0.f;
#pragma unroll
            for (int nb = 0; nb < 4; ++nb)
                *(float2*)(out + (long)row * rstr + c0 + nb * 8) =
                    make_float2(C[mt][nb][2 * h] + bv, C[mt][nb][2 * h + 1] + bv);
        }
    }
}

// ---------------- K0: weight prep --------------------------------------------
__global__ void prep_w(const float* Wr, const float* Wqw, const float* Wkw,
                       const float* Wvw, const float* Wqh, const float* Wkh,
                       const float* Wvh, const float* Wo) {
    const float* src[10] = {Wr, Wr, Wqw, Wkw, Wvw, Wqh, Wkh, Wvh, Wo, Wo};
    const int ro[10] = {0, 0, 0, 0, 0, 0, 0, 0, 0, 128};
    const int co[10] = {0, 128, 0, 0, 0, 0, 0, 0, 0, 0};
    const int ld[10] = {256, 256, 128, 128, 128, 128, 128, 128, 128, 128};
    int t = blockIdx.x;
    long tb = (long)t * 32768;
    for (int e = threadIdx.x; e < 16384; e += blockDim.x) {
        int r = e >> 7, c = e & 127;
        float v = src[t][(long)(r + ro[t]) * ld[t] + c + co[t]];
        __nv_bfloat16 h = __float2bfloat16(v);
        long o = tb + (swoff(r, c) >> 1);
        g_wt[o] = h;
        g_wt[o + 16384] = __float2bfloat16(v - __bfloat162float(h));
    }
}

// ---------------- K1: resize conv. grid (128,1,8) ----------------------------
// smem: W pair @0, X pair @65536, mbar @131072.
__global__ void __launch_bounds__(512, 1)
conv_resize(const float* __restrict__ x, const float* __restrict__ bias) {
    extern __shared__ char sm[];
    const int tid = threadIdx.x, lane = tid & 31, w = tid >> 5;
    const int wm = w >> 2, wn = w & 3;
    const uint32_t su = smem_u32(sm);
    const uint32_t mb = su + 131072;
    const int n0 = blockIdx.x * 128, b = blockIdx.z;

    if (tid == 0) MBI(mb, 1);
    __syncthreads();

    float C[2][4][4] = {};
    for (int kh = 0; kh < 2; ++kh) {
        if (tid == 0) {
            MBX(mb, PAIR_B);
            bulk_g2s(su, (const char*)g_wt + (size_t)kh * PAIR_B, PAIR_B, mb);
        }
        const float* g = x + (size_t)b * 256 * SL + (size_t)kh * 128 * SL + n0;
        for (int i = tid * 4; i < 16384; i += 2048) {
            int row = i >> 7, col = i & 127;
            float4 xv = *(const float4*)(g + (long)row * SL + col);
            __nv_bfloat16 h0 = __float2bfloat16(xv.x), h1 = __float2bfloat16(xv.y);
            __nv_bfloat16 h2 = __float2bfloat16(xv.z), h3 = __float2bfloat16(xv.w);
            __nv_bfloat16 l0 = __float2bfloat16(xv.x - __bfloat162float(h0));
            __nv_bfloat16 l1 = __float2bfloat16(xv.y - __bfloat162float(h1));
            __nv_bfloat16 l2 = __float2bfloat16(xv.z - __bfloat162float(h2));
            __nv_bfloat16 l3 = __float2bfloat16(xv.w - __bfloat162float(h3));
            char* p = sm + 65536 + swoff(row, col);
            *(uint2*)p = make_uint2(pkbf(h0, h1), pkbf(h2, h3));
            *(uint2*)(p + LO_B) = make_uint2(pkbf(l0, l1), pkbf(l2, l3));
        }
        MBW(mb, kh);
        __syncthreads();
        wgemm<true>(su, su + 65536, C, lane, wm, wn);
        __syncthreads();
    }
    // C[rf=r][col=w] for fixed h=n0>>7 -> g_res slice (b,r) tile[h][w]
    store_sw(C, (char*)g_res + (size_t)(b * 128) * PAIR_B, (uint32_t)(n0 >> 7),
             bias, lane, wm, wn);
}

// ---------------- K2: type-specialized QKV. grid 144 -------------------------
// type = blockIdx.x%3 (q/k/v), j = blockIdx.x/3; slices s = j + 48*i.
// smem: X0 @0, X1 @65536, W @131072, mbars @196608 (W, X0, X1).
__global__ void __launch_bounds__(512, 1)
qkv_t(const __nv_bfloat16* __restrict__ xin, int wbase,
      const float* __restrict__ b0, const float* __restrict__ b1,
      const float* __restrict__ b2, int bt) {
    extern __shared__ char sm[];
    const int tid = threadIdx.x, lane = tid & 31, w = tid >> 5;
    const int wm = w >> 2, wn = w & 3;
    const uint32_t su = smem_u32(sm);
    const uint32_t mW = su + 196608, mX0 = su + 196616, mX1 = su + 196624;
    const int t = blockIdx.x % 3;
    const int j = blockIdx.x / 3;
    const float* bias = (t == 0) ? b0 : (t == 1) ? b1 : b2;
    __nv_bfloat16* outp = (t == 0) ? g_q : (t == 1) ? g_k : g_v;

    if (tid == 0) { MBI(mW, 1); MBI(mX0, 1); MBI(mX1, 1); }
    __syncthreads();
    if (tid == 0) {
        MBX(mW, PAIR_B);
        bulk_g2s(su + 131072, (const char*)g_wt + (size_t)(wbase + t) * PAIR_B,
                 PAIR_B, mW);
        MBX(mX0, PAIR_B);
        bulk_g2s(su, (const char*)xin + (size_t)j * PAIR_B, PAIR_B, mX0);
    }
    int ph[2] = {0, 0};
    int it = 0;
    for (int s = j; s < 1024; s += 48, ++it) {
        const int cur = it & 1;
        const uint32_t mX = cur ? mX1 : mX0;
        const uint32_t oX = cur ? 65536u : 0u;
        const int nxt = s + 48;
        if (nxt < 1024 && tid == 0) {       // other buffer free since iter it-1
            const uint32_t mo = cur ? mX0 : mX1;
            MBX(mo, PAIR_B);
            bulk_g2s(su + (cur ? 0u : 65536u), (const char*)xin + (size_t)nxt * PAIR_B,
                     PAIR_B, mo);
        }
        if (it == 0) MBW(mW, 0);
        MBW(mX, ph[cur]);
        ph[cur] ^= 1;

        float C[2][4][4] = {};
        if (bt) wgemm<true>(su + 131072, su + oX, C, lane, wm, wn);
        else    wgemm<false>(su + 131072, su + oX, C, lane, wm, wn);
        __syncthreads();                    // Xcur free before next prefetch targets it
        const int b = s >> 7;
        store_sw(C, (char*)outp + (size_t)(b * 128) * PAIR_B, (uint32_t)(s & 127),
                 bias, lane, wm, wn);
    }
}

// ---------------- K3: persistent attention. grid NSM -------------------------
// smem: 3 pairs @0/65536/131072, mbars @196608, red @196640, red2 @198688.
__global__ void __launch_bounds__(512, 1)
attn_p(int mode) {
    extern __shared__ char sm[];
    const int tid = threadIdx.x, lane = tid & 31, w = tid >> 5;
    const int wm = w >> 2, wn = w & 3;
    const uint32_t su = smem_u32(sm);
    float* red  = (float*)(sm + 196640);
    float* red2 = (float*)(sm + 198688);
    const int G = gridDim.x;

    int ph[3] = {0, 0, 0};
    int iq = 0, ik = 1;
    const int iv = 2;
    if (tid == 0) { MBI(su + 196608, 1); MBI(su + 196616, 1); MBI(su + 196624, 1); }
    __syncthreads();
#define ABUF(i) (su + (uint32_t)(i) * 65536u)
#define AMB(i)  (su + 196608u + (uint32_t)(i) * 8u)
#define ALOAD(i, srcp) do { if (tid == 0) { MBX(AMB(i), PAIR_B); \
        bulk_g2s(ABUF(i), (srcp), PAIR_B, AMB(i)); } } while (0)

    {
        const int s0 = blockIdx.x;
        ALOAD(0, (const char*)g_q + (size_t)s0 * PAIR_B);
        ALOAD(1, (const char*)g_k + (size_t)s0 * PAIR_B);
        ALOAD(2, (const char*)g_v + (size_t)s0 * PAIR_B);
    }
    for (int s = blockIdx.x; s < 1024; s += G) {
        const int nxt = s + G;
        const int b = s >> 7, o = s & 127;

        MBW(AMB(iq), ph[iq]); ph[iq] ^= 1;
        MBW(AMB(ik), ph[ik]); ph[ik] ^= 1;
        float C[2][4][4] = {};
        wgemm<false>(ABUF(iq), ABUF(ik), C, lane, wm, wn);     // S = Q K^T
        __syncthreads();
        if (nxt < 1024) ALOAD(ik, (const char*)g_q + (size_t)nxt * PAIR_B);

        // ---- softmax; P -> iq buffer ----
        int rows_[2][2];
        float inv_[2][2];
#pragma unroll
        for (int mt = 0; mt < 2; ++mt)
#pragma unroll
            for (int h = 0; h < 2; ++h) {
                int row = wm * 32 + mt * 16 + (lane >> 2) + h * 8;
                rows_[mt][h] = row;
                float m = -3.4e38f;
#pragma unroll
                for (int nb = 0; nb < 4; ++nb)
                    m = fmaxf(m, fmaxf(C[mt][nb][2 * h], C[mt][nb][2 * h + 1]));
                m = fmaxf(m, __shfl_xor_sync(0xffffffffu, m, 1));
                m = fmaxf(m, __shfl_xor_sync(0xffffffffu, m, 2));
                if ((lane & 3) == 0) red[wn * 128 + row] = m;
            }
        __syncthreads();
#pragma unroll
        for (int mt = 0; mt < 2; ++mt)
#pragma unroll
            for (int h = 0; h < 2; ++h) {
                int row = rows_[mt][h];
                float m = fmaxf(fmaxf(red[row], red[128 + row]),
                                fmaxf(red[256 + row], red[384 + row]));
                float sum = 0.f;
#pragma unroll
                for (int nb = 0; nb < 4; ++nb) {
                    float e0 = __expf(C[mt][nb][2 * h] - m);
                    float e1 = __expf(C[mt][nb][2 * h + 1] - m);
                    C[mt][nb][2 * h] = e0;
                    C[mt][nb][2 * h + 1] = e1;
                    sum += e0 + e1;
                }
                sum += __shfl_xor_sync(0xffffffffu, sum, 1);
                sum += __shfl_xor_sync(0xffffffffu, sum, 2);
                if ((lane & 3) == 0) red2[wn * 128 + row] = sum;
            }
        __syncthreads();
#pragma unroll
        for (int mt = 0; mt < 2; ++mt)
#pragma unroll
            for (int h = 0; h < 2; ++h) {
                int row = rows_[mt][h];
                inv_[mt][h] = 1.f / (red2[row] + red2[128 + row] +
                                     red2[256 + row] + red2[384 + row]);
            }
        const int c0 = wn * 32 + 2 * (lane & 3);
        char* pbuf = sm + (size_t)iq * 65536;
#pragma unroll
        for (int mt = 0; mt < 2; ++mt)
#pragma unroll
            for (int h = 0; h < 2; ++h) {
                int row = rows_[mt][h];
                float iv2 = inv_[mt][h];
#pragma unroll
                for (int nb = 0; nb < 4; ++nb) {
                    float p0 = C[mt][nb][2 * h] * iv2, p1 = C[mt][nb][2 * h + 1] * iv2;
                    __nv_bfloat16 h0 = __float2bfloat16(p0), h1 = __float2bfloat16(p1);
                    __nv_bfloat16 l0 = __float2bfloat16(p0 - __bfloat162float(h0));
                    __nv_bfloat16 l1 = __float2bfloat16(p1 - __bfloat162float(h1));
                    char* pp = pbuf + swoff(row, c0 + nb * 8);
                    *(uint32_t*)pp = pkbf(h0, h1);
                    *(uint32_t*)(pp + LO_B) = pkbf(l0, l1);
                }
            }
        FENCE_ASY();                       // P (generic) ordered before later bulk into iq
        MBW(AMB(iv), ph[iv]); ph[iv] ^= 1;
        __syncthreads();                   // P visible to all warps

        float O[2][4][4] = {};
        wgemm<true>(ABUF(iq), ABUF(iv), O, lane, wm, wn);      // O = P V
        __syncthreads();
        if (nxt < 1024) {
            ALOAD(iq, (const char*)g_k + (size_t)nxt * PAIR_B);
            ALOAD(iv, (const char*)g_v + (size_t)nxt * PAIR_B);
        }
        if (mode == 0) {
            // O[r][w] -> g_wa slice (b, r=rf) tile[row=o][col=w]
            store_sw(O, (char*)g_wa + (size_t)(b * 128) * PAIR_B, (uint32_t)o,
                     nullptr, lane, wm, wn);
        } else {
            store_f32(O, g_att2 + (size_t)s * SL, 128, nullptr, lane, wm, wn);
        }
        int t2 = iq; iq = ik; ik = t2;     // Q(nxt) sits in old K buffer
    }
#undef ABUF
#undef AMB
#undef ALOAD
}

// ---------------- K4: transpose att2 -> g_ha tile-pairs ----------------------
// att2[b][o][r][h] -> g_ha tile (b*128+h): [row=r][col=o]
__global__ void trans_k(const float* __restrict__ in) {
    __shared__ float t[32][33];
    const int slice = blockIdx.z;
    const int b = slice >> 7, r = slice & 127;
    const int o0 = blockIdx.x * 32, h0 = blockIdx.y * 32;
#pragma unroll
    for (int i = threadIdx.y; i < 32; i += 8)
        t[i][threadIdx.x] =
            in[(((size_t)b * 128 + o0 + i) * 128 + r) * 128 + h0 + threadIdx.x];
    __syncthreads();
#pragma unroll
    for (int i = threadIdx.y; i < 32; i += 8) {
        float v = t[threadIdx.x][i];
        int h = h0 + i, col = o0 + threadIdx.x;
        char* base = (char*)g_ha + (size_t)(b * 128 + h) * PAIR_B + swoff(r, col);
        __nv_bfloat16 hh = __float2bfloat16(v);
        *(__nv_bfloat16*)base = hh;
        *(__nv_bfloat16*)(base + LO_B) = __float2bfloat16(v - __bfloat162float(hh));
    }
}

// ---------------- K5: persistent restore conv. grid NSM ----------------------
// work wk in [0,2048): m0i=wk&1, rest=wk>>1, b=rest>>7, nchunk=rest&127.
__global__ void __launch_bounds__(512, 1)
restore_p(float* __restrict__ out, const float* __restrict__ bias) {
    extern __shared__ char sm[];
    const int tid = threadIdx.x, lane = tid & 31, w = tid >> 5;
    const int wm = w >> 2, wn = w & 3;
    const uint32_t su = smem_u32(sm);
    const uint32_t mW = su + 196608, mX0 = su + 196616, mX1 = su + 196624;
    const int G = gridDim.x;
    const int m0i = blockIdx.x & 1, m0 = m0i * 128;   // G even -> constant per CTA

    if (tid == 0) { MBI(mW, 1); MBI(mX0, 1); MBI(mX1, 1); }
    __syncthreads();
    if (tid == 0) {
        MBX(mW, PAIR_B);
        bulk_g2s(su + 131072, (const char*)g_wt + (size_t)(8 + m0i) * PAIR_B, PAIR_B, mW);
        int rest0 = blockIdx.x >> 1;
        MBX(mX0, PAIR_B);
        bulk_g2s(su, (const char*)g_ha + (size_t)((rest0 >> 7) * 128 + (rest0 & 127)) * PAIR_B,
                 PAIR_B, mX0);
        int w1 = blockIdx.x + G;
        if (w1 < 2048) {
            int rest1 = w1 >> 1;
            MBX(mX1, PAIR_B);
            bulk_g2s(su + 65536,
                     (const char*)g_ha + (size_t)((rest1 >> 7) * 128 + (rest1 & 127)) * PAIR_B,
                     PAIR_B, mX1);
        }
    }
    int ph[2] = {0, 0};
    int it = 0;
    for (int wk = blockIdx.x; wk < 2048; wk += G, ++it) {
        const int cur = it & 1;
        const uint32_t mX = cur ? mX1 : mX0;
        const uint32_t oX = cur ? 65536u : 0u;
        if (it == 0) MBW(mW, 0);
        MBW(mX, ph[cur]);
        ph[cur] ^= 1;

        float C[2][4][4] = {};
        wgemm<true>(su + 131072, su + oX, C, lane, wm, wn);
        __syncthreads();
        const int nxt2 = wk + 2 * G;
        if (nxt2 < 2048 && tid == 0) {
            int rest2 = nxt2 >> 1;
            MBX(mX, PAIR_B);
            bulk_g2s(su + oX,
                     (const char*)g_ha + (size_t)((rest2 >> 7) * 128 + (rest2 & 127)) * PAIR_B,
                     PAIR_B, mX);
        }
        const int rest = wk >> 1, b = rest >> 7, n0 = (rest & 127) * 128;
        store_f32(C, out + (size_t)b * 256 * SL + (size_t)m0 * SL + n0, SL,
                  bias + m0, lane, wm, wn);
    }
}

// ---------------------------------------------------------------------------
extern "C" void kernel_launch(void* const* d_in, const int* in_sizes, int n_in,
                              void* d_out, int out_size) {
    const float* x   = (const float*)d_in[0];
    const float* Wr  = (const float*)d_in[1];
    const float* br  = (const float*)d_in[2];
    const float* Wqw = (const float*)d_in[3];
    const float* bqw = (const float*)d_in[4];
    const float* Wkw = (const float*)d_in[5];
    const float* bkw = (const float*)d_in[6];
    const float* Wvw = (const float*)d_in[7];
    const float* bvw = (const float*)d_in[8];
    const float* Wqh = (const float*)d_in[9];
    const float* bqh = (const float*)d_in[10];
    const float* Wkh = (const float*)d_in[11];
    const float* bkh = (const float*)d_in[12];
    const float* Wvh = (const float*)d_in[13];
    const float* bvh = (const float*)d_in[14];
    const float* Wo  = (const float*)d_in[15];
    const float* bo  = (const float*)d_in[16];
    float* out = (float*)d_out;

    void* p;
    cudaGetSymbolAddress(&p, g_att2);
    float* att2 = (float*)p;
    void* pres; cudaGetSymbolAddress(&pres, g_res);
    void* pwa;  cudaGetSymbolAddress(&pwa, g_wa);

    const int SM_CONV = 131072 + 64;
    const int SM_BIG  = 196608 + 64;
    const int SM_ATT  = 196608 + 4096 + 128;
    cudaFuncSetAttribute((const void*)conv_resize,
                         cudaFuncAttributeMaxDynamicSharedMemorySize, SM_CONV);
    cudaFuncSetAttribute((const void*)qkv_t,
                         cudaFuncAttributeMaxDynamicSharedMemorySize, SM_BIG);
    cudaFuncSetAttribute((const void*)attn_p,
                         cudaFuncAttributeMaxDynamicSharedMemorySize, SM_ATT);
    cudaFuncSetAttribute((const void*)restore_p,
                         cudaFuncAttributeMaxDynamicSharedMemorySize, SM_BIG);

    prep_w<<<10, 256>>>(Wr, Wqw, Wkw, Wvw, Wqh, Wkh, Wvh, Wo);
    conv_resize<<<dim3(128, 1, 8), 512, SM_CONV>>>(x, br);
    // width qkv (bt=1): X = g_res tiles, weights 2,3,4
    qkv_t<<<144, 512, SM_BIG>>>((const __nv_bfloat16*)pres, 2, bqw, bkw, bvw, 1);
    attn_p<<<NSM, 512, SM_ATT>>>(0);
    // height qkv (bt=0): X = g_wa tiles, weights 5,6,7
    qkv_t<<<144, 512, SM_BIG>>>((const __nv_bfloat16*)pwa, 5, bqh, bkh, bvh, 0);
    attn_p<<<NSM, 512, SM_ATT>>>(1);
    trans_k<<<dim3(4, 4, 1024), dim3(32, 8)>>>(att2);
    restore_p<<<NSM, 512, SM_BIG>>>(out, bo);
}